// round 2
// baseline (speedup 1.0000x reference)
#include <cuda_runtime.h>
#include <cuda_bf16.h>

// GRNN scan: B=512, T=8192, state dim 2.
//
// Key structure: the covariance (Riccati) recursion is batch-independent and
// symmetric, so a single producer thread computes the shared per-step
// coefficient X_t = cov_t @ C^T + D^T once. 512 consumer threads (one per
// batch row) then run the cheap 2-dim state recursion:
//     out_t = dt*C @ x_t                      (pre-update state)
//     x_{t+1} = x_t + clip(dt*A @ x_t + X_t @ (dy_t - out_t), +-0.1)
// which is the reference dx = (A - xicov@C)@x*dt + xicov@dy, reassociated.

#define T_STEPS 8192
#define NBATCH  512
#define DTF     1e-3f
#define CLIPX   0.1f
#define UG      8          // steps per prefetch group in the consumer

__device__ float4 g_X[T_STEPS];   // X_t = (x00, x01, x10, x11)

// ---------------------------------------------------------------------------
// Producer: single thread, batch-independent symmetric Riccati recursion.
// cov tracked as (p00, p01, p11); stays symmetric because cov0 = I and the
// given D is symmetric (all update terms preserve symmetry; clip elementwise).
// ---------------------------------------------------------------------------
__global__ void riccati_kernel(const float* __restrict__ A,
                               const float* __restrict__ C,
                               const float* __restrict__ D) {
    if (threadIdx.x != 0) return;
    const float a00 = A[0], a01 = A[1], a10 = A[2], a11 = A[3];
    const float c00 = C[0], c01 = C[1], c10 = C[2], c11 = C[3];
    const float d00 = D[0], d01 = D[1], d10 = D[2], d11 = D[3];

    float p00 = 1.0f, p01 = 0.0f, p11 = 1.0f;   // cov0 = I

    for (int t = 0; t < T_STEPS; ++t) {
        // xicov = cov @ C^T + D^T
        // (cov@Ct)[i][j] = sum_k cov[i][k] * C[j][k];  Dt[i][j] = D[j][i]
        float x00 = fmaf(p00, c00, fmaf(p01, c01, d00));
        float x01 = fmaf(p00, c10, fmaf(p01, c11, d10));
        float x10 = fmaf(p01, c00, fmaf(p11, c01, d01));
        float x11 = fmaf(p01, c10, fmaf(p11, c11, d11));
        g_X[t] = make_float4(x00, x01, x10, x11);

        // S = A@cov + cov@A^T   (symmetric)
        float s00 = 2.0f * fmaf(a00, p00, a01 * p01);
        float s01 = fmaf(a00, p01, a01 * p11) + fmaf(a10, p00, a11 * p01);
        float s11 = 2.0f * fmaf(a10, p01, a11 * p11);

        // M = xicov @ xicov^T   (symmetric)
        float m00 = fmaf(x00, x00, x01 * x01);
        float m01 = fmaf(x00, x10, x01 * x11);
        float m11 = fmaf(x10, x10, x11 * x11);

        // cov += dt * (S + D - M), clipped to [-1, 1]
        p00 = fmaf(DTF, s00 + d00 - m00, p00);
        p01 = fmaf(DTF, s01 + d01 - m01, p01);
        p11 = fmaf(DTF, s11 + d11 - m11, p11);
        p00 = fminf(fmaxf(p00, -1.0f), 1.0f);
        p01 = fminf(fmaxf(p01, -1.0f), 1.0f);
        p11 = fminf(fmaxf(p11, -1.0f), 1.0f);
    }
}

// ---------------------------------------------------------------------------
// Consumer: one thread per batch row. 16 CTAs x 32 threads so each warp owns
// an SM (no issue contention). Software-pipelined prefetch of X_t (shared
// coefficient, float4) and dy (per-row float2) in groups of UG steps,
// double-buffered so the next group's loads overlap this group's compute.
// ---------------------------------------------------------------------------
struct Grp {
    float4 X[UG];
    float2 dy[UG];
};

__device__ __forceinline__ void load_grp(int t, const float2* __restrict__ dy,
                                         Grp& g) {
#pragma unroll
    for (int i = 0; i < UG; ++i) {
        g.X[i]  = g_X[t + i];
        g.dy[i] = __ldg(&dy[t + i]);
    }
}

__device__ __forceinline__ void run_grp(const Grp& g, int t,
                                        float2* __restrict__ o,
                                        float a00, float a01, float a10, float a11,
                                        float c00, float c01, float c10, float c11,
                                        float& x0, float& x1) {
#pragma unroll
    for (int i = 0; i < UG; ++i) {
        // out = dt*C @ x  (C pre-scaled by dt)
        float v0 = fmaf(c00, x0, c01 * x1);
        float v1 = fmaf(c10, x0, c11 * x1);
        o[t + i] = make_float2(v0, v1);

        float u0 = g.dy[i].x - v0;
        float u1 = g.dy[i].y - v1;

        // dx = dt*A @ x + X @ u   (A pre-scaled by dt)
        float dx0 = fmaf(a00, x0, fmaf(a01, x1, fmaf(g.X[i].x, u0, g.X[i].y * u1)));
        float dx1 = fmaf(a10, x0, fmaf(a11, x1, fmaf(g.X[i].z, u0, g.X[i].w * u1)));

        dx0 = fminf(fmaxf(dx0, -CLIPX), CLIPX);
        dx1 = fminf(fmaxf(dx1, -CLIPX), CLIPX);
        x0 += dx0;
        x1 += dx1;
    }
}

__global__ void __launch_bounds__(32, 1)
scan_kernel(const float* __restrict__ inputs,
            const float* __restrict__ A,
            const float* __restrict__ C,
            float* __restrict__ out) {
    const int b = blockIdx.x * 32 + threadIdx.x;   // batch row

    const float a00 = DTF * A[0], a01 = DTF * A[1];
    const float a10 = DTF * A[2], a11 = DTF * A[3];
    const float c00 = DTF * C[0], c01 = DTF * C[1];
    const float c10 = DTF * C[2], c11 = DTF * C[3];

    const float2* dy = (const float2*)inputs + (size_t)b * T_STEPS;
    float2*       o  = (float2*)out + (size_t)b * T_STEPS;

    float x0 = 1.0f, x1 = 0.0f;                    // x0 = [1, 0]

    Grp ga, gb;
    load_grp(0, dy, ga);

    for (int t = 0; t < T_STEPS; t += 2 * UG) {
        load_grp(t + UG, dy, gb);
        run_grp(ga, t, o, a00, a01, a10, a11, c00, c01, c10, c11, x0, x1);
        if (t + 2 * UG < T_STEPS) load_grp(t + 2 * UG, dy, ga);
        run_grp(gb, t + UG, o, a00, a01, a10, a11, c00, c01, c10, c11, x0, x1);
    }
}

// ---------------------------------------------------------------------------
extern "C" void kernel_launch(void* const* d_in, const int* in_sizes, int n_in,
                              void* d_out, int out_size) {
    const float* inputs = (const float*)d_in[0];   // [512, 8192, 2]
    const float* A      = (const float*)d_in[1];   // [2,2]
    const float* C      = (const float*)d_in[2];   // [2,2]
    const float* D      = (const float*)d_in[3];   // [2,2]
    float*       out    = (float*)d_out;           // [512, 8192, 2]

    riccati_kernel<<<1, 32>>>(A, C, D);
    scan_kernel<<<NBATCH / 32, 32>>>(inputs, A, C, out);
}